// round 2
// baseline (speedup 1.0000x reference)
#include <cuda_runtime.h>

#define T_LEN 64000
#define NB 4
#define CH 128
#define NCLS 256

// ---------------- device scratch (static, no allocations) ----------------
__device__ float g_buf0[NB * CH * T_LEN];           // 131 MB
__device__ float g_buf1[NB * CH * T_LEN];           // 131 MB
__device__ float g_wt[27 * 2 * CH * CH];            // transposed layer weights [L][k=tap*128+c][oc]
__device__ float g_wtc[CH * NCLS];                  // transposed classifier [c][cls]

// ---------------- packed f32x2 helpers ----------------
__device__ __forceinline__ unsigned long long fma2(unsigned long long a,
                                                   unsigned long long b,
                                                   unsigned long long c) {
    unsigned long long d;
    asm("fma.rn.f32x2 %0, %1, %2, %3;" : "=l"(d) : "l"(a), "l"(b), "l"(c));
    return d;
}
__device__ __forceinline__ unsigned long long pack2(float lo, float hi) {
    unsigned long long r;
    asm("mov.b64 %0, {%1, %2};" : "=l"(r) : "f"(lo), "f"(hi));
    return r;
}
__device__ __forceinline__ void unpack2(float& lo, float& hi, unsigned long long v) {
    asm("mov.b64 {%0, %1}, %2;" : "=f"(lo), "=f"(hi) : "l"(v));
}

// ---------------- weight transpose prep ----------------
// g_wt[L][tap*128+c][o] = w_rest[L][o][c][tap]
// g_wtc[c][o]           = w_cls[o][c]
__global__ void prep_kernel(const float* __restrict__ w_rest,
                            const float* __restrict__ w_cls,
                            float* __restrict__ wt,
                            float* __restrict__ wtc) {
    int idx = blockIdx.x * blockDim.x + threadIdx.x;
    const int nL = 27 * 256 * 128;
    if (idx < nL) {
        int L = idx / (256 * 128);
        int r = idx % (256 * 128);
        int k = r / 128;
        int o = r % 128;
        int tap = k >> 7;
        int c = k & 127;
        wt[idx] = w_rest[((L * 128 + o) * 128 + c) * 2 + tap];
    }
    if (idx < 128 * 256) {
        int c = idx / 256;
        int o = idx % 256;
        wtc[idx] = w_cls[o * 128 + c];
    }
}

// ---------------- layer 0: 1 input channel, d=1 ----------------
__global__ void layer0_kernel(const float* __restrict__ seq,
                              const float* __restrict__ wf,
                              float* __restrict__ y) {
    int t = blockIdx.x * blockDim.x + threadIdx.x;
    int o = blockIdx.y;
    int n = blockIdx.z;
    if (t >= T_LEN) return;
    const float* xs = seq + n * T_LEN;
    float x1 = xs[t];
    float x0 = (t >= 1) ? xs[t - 1] : 0.f;
    float v = wf[o * 2] * x0 + wf[o * 2 + 1] * x1;
    y[(n * CH + o) * T_LEN + t] = fmaxf(v, 0.f);
}

// ---------------- dilated conv layer as GEMM ----------------
// Y[n, oc, t] = relu( sum_{k=0..255} Ws[k][oc] * X[k][t] )
// X rows k<128: x[n][k][t-d]; k>=128: x[n][k-128][t]
__global__ void __launch_bounds__(256) layer_gemm(
    const float* __restrict__ x, const float* __restrict__ wt,
    float* __restrict__ y, int d) {
    __shared__ __align__(16) float Ws[64][128];  // 32 KB
    __shared__ __align__(16) float Xs[64][64];   // 16 KB

    const int n = blockIdx.y;
    const int t0 = blockIdx.x * 64;
    const float* xn = x + n * CH * T_LEN;
    float* yn = y + n * CH * T_LEN;

    const int tid = threadIdx.x;
    const int tx = tid & 15;          // t group
    const int ty = tid >> 4;          // oc group
    const int oc0 = ty * 8;
    const int tl0 = tx * 4;

    unsigned long long acc[4][4];
#pragma unroll
    for (int p = 0; p < 4; p++)
#pragma unroll
        for (int j = 0; j < 4; j++) acc[p][j] = 0ull;

    for (int kk = 0; kk < 4; kk++) {
        const int k0 = kk * 64;
        // --- load weight chunk: [64][128] floats, coalesced float4 ---
#pragma unroll
        for (int it = 0; it < 8; it++) {
            int idx = it * 256 + tid;        // float4 index, 0..2047
            int kl = idx >> 5;               // 32 float4 per row
            int o4 = idx & 31;
            *(float4*)&Ws[kl][o4 * 4] =
                *(const float4*)&wt[(k0 + kl) * 128 + o4 * 4];
        }
        // --- load activation chunk: [64][64], scalar (t-d may misalign) ---
#pragma unroll
        for (int it = 0; it < 16; it++) {
            int idx = it * 256 + tid;
            int kl = idx >> 6;
            int j = idx & 63;
            int kg = k0 + kl;
            int ch = kg & 127;
            int tt = t0 + j - ((kg < 128) ? d : 0);
            Xs[kl][j] = (tt >= 0) ? xn[ch * T_LEN + tt] : 0.f;
        }
        __syncthreads();

#pragma unroll 16
        for (int k = 0; k < 64; k++) {
            float4 a0 = *(float4*)&Ws[k][oc0];
            float4 a1 = *(float4*)&Ws[k][oc0 + 4];
            float4 xb = *(float4*)&Xs[k][tl0];
            unsigned long long A[4], B[4];
            A[0] = pack2(a0.x, a0.y);
            A[1] = pack2(a0.z, a0.w);
            A[2] = pack2(a1.x, a1.y);
            A[3] = pack2(a1.z, a1.w);
            B[0] = pack2(xb.x, xb.x);
            B[1] = pack2(xb.y, xb.y);
            B[2] = pack2(xb.z, xb.z);
            B[3] = pack2(xb.w, xb.w);
#pragma unroll
            for (int p = 0; p < 4; p++)
#pragma unroll
                for (int j = 0; j < 4; j++)
                    acc[p][j] = fma2(A[p], B[j], acc[p][j]);
        }
        __syncthreads();
    }

    // --- epilogue: relu + float4 stores (coalesced along t) ---
#pragma unroll
    for (int p = 0; p < 4; p++) {
        float lo[4], hi[4];
#pragma unroll
        for (int j = 0; j < 4; j++) unpack2(lo[j], hi[j], acc[p][j]);
        float4 v0 = make_float4(fmaxf(lo[0], 0.f), fmaxf(lo[1], 0.f),
                                fmaxf(lo[2], 0.f), fmaxf(lo[3], 0.f));
        float4 v1 = make_float4(fmaxf(hi[0], 0.f), fmaxf(hi[1], 0.f),
                                fmaxf(hi[2], 0.f), fmaxf(hi[3], 0.f));
        *(float4*)&yn[(oc0 + 2 * p) * T_LEN + t0 + tl0] = v0;
        *(float4*)&yn[(oc0 + 2 * p + 1) * T_LEN + t0 + tl0] = v1;
    }
}

// ---------------- classifier: 128 -> 256, + bias, no relu ----------------
__global__ void __launch_bounds__(256) cls_gemm(
    const float* __restrict__ x, const float* __restrict__ wtc,
    const float* __restrict__ bias, float* __restrict__ out) {
    __shared__ __align__(16) float Ws[64][128];
    __shared__ __align__(16) float Xs[64][64];

    const int n = blockIdx.y;
    const int m0 = blockIdx.z * 128;
    const int t0 = blockIdx.x * 64;
    const float* xn = x + n * CH * T_LEN;
    float* yn = out + n * NCLS * T_LEN;

    const int tid = threadIdx.x;
    const int tx = tid & 15;
    const int ty = tid >> 4;
    const int oc0 = ty * 8;
    const int tl0 = tx * 4;

    unsigned long long acc[4][4];
#pragma unroll
    for (int p = 0; p < 4; p++)
#pragma unroll
        for (int j = 0; j < 4; j++) acc[p][j] = 0ull;

    for (int kk = 0; kk < 2; kk++) {
        const int k0 = kk * 64;
#pragma unroll
        for (int it = 0; it < 8; it++) {
            int idx = it * 256 + tid;   // float4 index 0..2047
            int kl = idx >> 5;
            int o4 = idx & 31;
            *(float4*)&Ws[kl][o4 * 4] =
                *(const float4*)&wtc[(k0 + kl) * 256 + m0 + o4 * 4];
        }
#pragma unroll
        for (int it = 0; it < 4; it++) {
            int idx = it * 256 + tid;   // float4 index 0..1023
            int kl = idx >> 4;          // 16 float4 per row
            int j4 = idx & 15;
            *(float4*)&Xs[kl][j4 * 4] =
                *(const float4*)&xn[(k0 + kl) * T_LEN + t0 + j4 * 4];
        }
        __syncthreads();

#pragma unroll 16
        for (int k = 0; k < 64; k++) {
            float4 a0 = *(float4*)&Ws[k][oc0];
            float4 a1 = *(float4*)&Ws[k][oc0 + 4];
            float4 xb = *(float4*)&Xs[k][tl0];
            unsigned long long A[4], B[4];
            A[0] = pack2(a0.x, a0.y);
            A[1] = pack2(a0.z, a0.w);
            A[2] = pack2(a1.x, a1.y);
            A[3] = pack2(a1.z, a1.w);
            B[0] = pack2(xb.x, xb.x);
            B[1] = pack2(xb.y, xb.y);
            B[2] = pack2(xb.z, xb.z);
            B[3] = pack2(xb.w, xb.w);
#pragma unroll
            for (int p = 0; p < 4; p++)
#pragma unroll
                for (int j = 0; j < 4; j++)
                    acc[p][j] = fma2(A[p], B[j], acc[p][j]);
        }
        __syncthreads();
    }

#pragma unroll
    for (int p = 0; p < 4; p++) {
        float bl = bias[m0 + oc0 + 2 * p];
        float bh = bias[m0 + oc0 + 2 * p + 1];
        float lo[4], hi[4];
#pragma unroll
        for (int j = 0; j < 4; j++) unpack2(lo[j], hi[j], acc[p][j]);
        float4 v0 = make_float4(lo[0] + bl, lo[1] + bl, lo[2] + bl, lo[3] + bl);
        float4 v1 = make_float4(hi[0] + bh, hi[1] + bh, hi[2] + bh, hi[3] + bh);
        *(float4*)&yn[(m0 + oc0 + 2 * p) * T_LEN + t0 + tl0] = v0;
        *(float4*)&yn[(m0 + oc0 + 2 * p + 1) * T_LEN + t0 + tl0] = v1;
    }
}

// ---------------- launch ----------------
extern "C" void kernel_launch(void* const* d_in, const int* in_sizes, int n_in,
                              void* d_out, int out_size) {
    (void)in_sizes; (void)n_in; (void)out_size;
    const float* seq     = (const float*)d_in[0];
    const float* w_first = (const float*)d_in[1];
    const float* w_rest  = (const float*)d_in[2];
    const float* w_cls   = (const float*)d_in[3];
    const float* b_cls   = (const float*)d_in[4];
    float* out = (float*)d_out;

    float *buf0, *buf1, *wt, *wtc;
    cudaGetSymbolAddress((void**)&buf0, g_buf0);
    cudaGetSymbolAddress((void**)&buf1, g_buf1);
    cudaGetSymbolAddress((void**)&wt,  g_wt);
    cudaGetSymbolAddress((void**)&wtc, g_wtc);

    // transpose weights
    prep_kernel<<<(27 * 256 * 128 + 255) / 256, 256>>>(w_rest, w_cls, wt, wtc);

    // layer 0 (1 input channel, d = 1)
    layer0_kernel<<<dim3(T_LEN / 256, CH, NB), 256>>>(seq, w_first, buf0);

    // layers 1..27
    for (int i = 1; i < 28; i++) {
        int l = i % 14;
        int d = 1 << (l % 10);
        const float* src = (i & 1) ? buf0 : buf1;
        float* dst       = (i & 1) ? buf1 : buf0;
        layer_gemm<<<dim3(T_LEN / 64, NB), 256>>>(
            src, wt + (size_t)(i - 1) * 256 * 128, dst, d);
    }

    // classifier (layer 27 output lives in buf1)
    cls_gemm<<<dim3(T_LEN / 64, NB, 2), 256>>>(buf1, wtc, b_cls, out);
}

// round 4
// speedup vs baseline: 1.7549x; 1.7549x over previous
#include <cuda_runtime.h>
#include <cuda_bf16.h>
#include <cstdint>

#define T_LEN 64000
#define NB 4
#define CH 128
#define NCLS 256
#define CHUNK 32
#define NCHUNK 8
#define SPAN (CHUNK * NCHUNK)      // 256 t per CTA
#define NXCTA (T_LEN / SPAN)       // 250

// ---------------- static device buffers ----------------
// activations: bf16 planes, layout [n][plane][t][ch]
__device__ unsigned short g_act0[(size_t)NB * 2 * T_LEN * CH];
__device__ unsigned short g_act1[(size_t)NB * 2 * T_LEN * CH];
// layer weights, packed bf16x2 along ch pairs: [L][tap][m=oc][kp=ch/2]
__device__ uint32_t g_whi[27 * 2 * 128 * 64];
__device__ uint32_t g_wlo[27 * 2 * 128 * 64];
// classifier: [plane][m=cls 256][kp=ch/2]
__device__ uint32_t g_wc[2 * 256 * 64];

// ---------------- helpers ----------------
__device__ __forceinline__ uint32_t smem_u32(const void* p) {
    uint32_t a;
    asm("{ .reg .u64 t; cvta.to.shared.u64 t, %1; cvt.u32.u64 %0, t; }" : "=r"(a) : "l"(p));
    return a;
}
__device__ __forceinline__ void cpa16(uint32_t dst, const void* src, int sz) {
    asm volatile("cp.async.cg.shared.global [%0], [%1], 16, %2;"
                 :: "r"(dst), "l"(src), "r"(sz) : "memory");
}
#define CP_COMMIT() asm volatile("cp.async.commit_group;" ::: "memory")
#define CP_WAIT1()  asm volatile("cp.async.wait_group 1;" ::: "memory")
#define CP_WAIT0()  asm volatile("cp.async.wait_group 0;" ::: "memory")

__device__ __forceinline__ void mma16816(float c[4], const uint32_t a[4],
                                         uint32_t b0, uint32_t b1) {
    asm volatile(
        "mma.sync.aligned.m16n8k16.row.col.f32.bf16.bf16.f32 "
        "{%0,%1,%2,%3}, {%4,%5,%6,%7}, {%8,%9}, {%0,%1,%2,%3};"
        : "+f"(c[0]), "+f"(c[1]), "+f"(c[2]), "+f"(c[3])
        : "r"(a[0]), "r"(a[1]), "r"(a[2]), "r"(a[3]), "r"(b0), "r"(b1));
}

// ---------------- prep: split + pack weights ----------------
__device__ __forceinline__ uint32_t pack_split(float w0, float w1, int plane) {
    __nv_bfloat16 h0 = __float2bfloat16(w0), h1 = __float2bfloat16(w1);
    if (plane == 0)
        return (uint32_t)__bfloat16_as_ushort(h0) |
               ((uint32_t)__bfloat16_as_ushort(h1) << 16);
    __nv_bfloat16 l0 = __float2bfloat16(w0 - __bfloat162float(h0));
    __nv_bfloat16 l1 = __float2bfloat16(w1 - __bfloat162float(h1));
    return (uint32_t)__bfloat16_as_ushort(l0) |
           ((uint32_t)__bfloat16_as_ushort(l1) << 16);
}

__global__ void prep_kernel(const float* __restrict__ wrest,
                            const float* __restrict__ wcls,
                            uint32_t* __restrict__ whi,
                            uint32_t* __restrict__ wlo,
                            uint32_t* __restrict__ wc) {
    int idx = blockIdx.x * blockDim.x + threadIdx.x;
    if (idx < 27 * 2 * 128 * 64) {
        int kp = idx & 63;
        int m = (idx >> 6) & 127;
        int tap = (idx >> 13) & 1;
        int L = idx >> 14;
        float w0 = wrest[((L * 128 + m) * 128 + kp * 2) * 2 + tap];
        float w1 = wrest[((L * 128 + m) * 128 + kp * 2 + 1) * 2 + tap];
        whi[idx] = pack_split(w0, w1, 0);
        wlo[idx] = pack_split(w0, w1, 1);
    }
    if (idx < 2 * 256 * 64) {
        int kp = idx & 63;
        int m = (idx >> 6) & 255;
        int pl = idx >> 14;
        float w0 = wcls[m * 128 + kp * 2];
        float w1 = wcls[m * 128 + kp * 2 + 1];
        wc[idx] = pack_split(w0, w1, pl);
    }
}

// ---------------- layer 0: 1 input channel, d = 1 ----------------
__global__ void layer0_kernel(const float* __restrict__ seq,
                              const float* __restrict__ wf,
                              unsigned short* __restrict__ actout) {
    int oc = threadIdx.x & 127;
    int half = threadIdx.x >> 7;
    int n = blockIdx.y;
    int t0 = blockIdx.x * 128 + half * 64;
    float w0 = wf[oc * 2], w1 = wf[oc * 2 + 1];
    const float* xs = seq + (size_t)n * T_LEN;
    unsigned short* ohi = actout + (size_t)(n * 2 + 0) * T_LEN * CH;
    unsigned short* olo = actout + (size_t)(n * 2 + 1) * T_LEN * CH;
    for (int j = 0; j < 64; j++) {
        int t = t0 + j;
        float x1 = xs[t];
        float x0 = (t >= 1) ? xs[t - 1] : 0.f;
        float y = fmaxf(w0 * x0 + w1 * x1, 0.f);
        __nv_bfloat16 h = __float2bfloat16(y);
        __nv_bfloat16 l = __float2bfloat16(y - __bfloat162float(h));
        ohi[(size_t)t * CH + oc] = __bfloat16_as_ushort(h);
        olo[(size_t)t * CH + oc] = __bfloat16_as_ushort(l);
    }
}

// ---------------- dilated-conv layer via mma.sync bf16 ----------------
// smem (u32 units):
//   [0, 17408)      Wl: [tap][m 128][68]
//   [17408, 34816)  X : [buf 2][tile 4 = tap*2+plane][r 32][68]
// CTA tile: 128 oc x 32 t per chunk, 8 chunks. 8 warps = 4(m) x 2(n).
__global__ void __launch_bounds__(256, 1) layer_mma(
    const unsigned short* __restrict__ actin,
    unsigned short* __restrict__ actout,
    const uint32_t* __restrict__ whi,
    const uint32_t* __restrict__ wlo, int d) {
    extern __shared__ uint32_t sm[];
    const uint32_t sb = smem_u32(sm);
    const int tid = threadIdx.x;
    const int lane = tid & 31, wid = tid >> 5;
    const int g = lane >> 2, tq = lane & 3;
    const int n = blockIdx.y;
    const int tbase = blockIdx.x * SPAN;
    const int m0 = (wid & 3) * 32;
    const int n0 = (wid >> 2) * 16;

    // ---- group 0: Wl -> smem
#pragma unroll
    for (int i = 0; i < 16; i++) {
        int idx = i * 256 + tid;        // 4096 segs
        int row = idx >> 4, seg = idx & 15;
        cpa16(sb + (row * 68 + seg * 4) * 4, wlo + row * 64 + seg * 4, 16);
    }
    CP_COMMIT();

    // ---- X chunk loader
    auto load_x = [&](int c) {
        int buf = c & 1;
        int tcb = tbase + c * CHUNK;
#pragma unroll
        for (int i = 0; i < 8; i++) {
            int idx = i * 256 + tid;    // 2048 segs
            int tile = idx >> 9, rem = idx & 511;
            int r = rem >> 4, seg = rem & 15;
            int tap = tile >> 1, pl = tile & 1;
            int t = tcb + r - (tap == 0 ? d : 0);
            const unsigned short* src =
                actin + ((size_t)(n * 2 + pl) * T_LEN + (t < 0 ? 0 : t)) * CH + seg * 8;
            cpa16(sb + (17408 + buf * 8704 + tile * 2176 + r * 68 + seg * 4) * 4,
                  src, t >= 0 ? 16 : 0);
        }
        CP_COMMIT();
    };
    load_x(0);
    load_x(1);

    // ---- preload Wh fragments into registers (chunk-invariant)
    uint32_t wh[2][8][2][4];
#pragma unroll
    for (int tap = 0; tap < 2; tap++)
#pragma unroll
        for (int ks = 0; ks < 8; ks++)
#pragma unroll
            for (int mt = 0; mt < 2; mt++) {
                const uint32_t* wp = whi + (tap * 128 + m0 + mt * 16) * 64;
                wh[tap][ks][mt][0] = wp[(g)*64 + ks * 8 + tq];
                wh[tap][ks][mt][1] = wp[(g + 8) * 64 + ks * 8 + tq];
                wh[tap][ks][mt][2] = wp[(g)*64 + ks * 8 + 4 + tq];
                wh[tap][ks][mt][3] = wp[(g + 8) * 64 + ks * 8 + 4 + tq];
            }

    CP_WAIT1();          // Wl + chunk0 complete (chunk1 in flight)
    __syncthreads();

#pragma unroll 1
    for (int c = 0; c < NCHUNK; c++) {
        const int buf = c & 1;
        const uint32_t* X = sm + 17408 + buf * 8704;

        float acc[2][2][4];
#pragma unroll
        for (int mt = 0; mt < 2; mt++)
#pragma unroll
            for (int nt = 0; nt < 2; nt++)
#pragma unroll
                for (int j = 0; j < 4; j++) acc[mt][nt][j] = 0.f;

        // -- passes 1,2: Wh (regs) x {Xh, Xl}
#pragma unroll
        for (int xpl = 0; xpl < 2; xpl++)
#pragma unroll
            for (int tap = 0; tap < 2; tap++) {
                const uint32_t* Xt = X + (tap * 2 + xpl) * 2176;
#pragma unroll
                for (int ks = 0; ks < 8; ks++) {
                    uint32_t b0[2], b1[2];
#pragma unroll
                    for (int nt = 0; nt < 2; nt++) {
                        const uint32_t* xr = Xt + (n0 + nt * 8 + g) * 68;
                        b0[nt] = xr[ks * 8 + tq];
                        b1[nt] = xr[ks * 8 + 4 + tq];
                    }
#pragma unroll
                    for (int mt = 0; mt < 2; mt++)
#pragma unroll
                        for (int nt = 0; nt < 2; nt++)
                            mma16816(acc[mt][nt], wh[tap][ks][mt], b0[nt], b1[nt]);
                }
            }

        // -- pass 3: Wl (smem) x Xh
#pragma unroll
        for (int tap = 0; tap < 2; tap++) {
            const uint32_t* Xt = X + (tap * 2 + 0) * 2176;
            const uint32_t* Wt = sm + tap * 8704;
#pragma unroll
            for (int ks = 0; ks < 8; ks++) {
                uint32_t a[2][4], b0[2], b1[2];
#pragma unroll
                for (int mt = 0; mt < 2; mt++) {
                    a[mt][0] = Wt[(m0 + mt * 16 + g) * 68 + ks * 8 + tq];
                    a[mt][1] = Wt[(m0 + mt * 16 + g + 8) * 68 + ks * 8 + tq];
                    a[mt][2] = Wt[(m0 + mt * 16 + g) * 68 + ks * 8 + 4 + tq];
                    a[mt][3] = Wt[(m0 + mt * 16 + g + 8) * 68 + ks * 8 + 4 + tq];
                }
#pragma unroll
                for (int nt = 0; nt < 2; nt++) {
                    const uint32_t* xr = Xt + (n0 + nt * 8 + g) * 68;
                    b0[nt] = xr[ks * 8 + tq];
                    b1[nt] = xr[ks * 8 + 4 + tq];
                }
#pragma unroll
                for (int mt = 0; mt < 2; mt++)
#pragma unroll
                    for (int nt = 0; nt < 2; nt++)
                        mma16816(acc[mt][nt], a[mt], b0[nt], b1[nt]);
            }
        }

        __syncthreads();  // all reads of X buf done -> reuse as stage

        // -- epilogue: relu + split, transpose through smem, coalesced store
        unsigned short* stg = (unsigned short*)(sm + 17408 + buf * 8704);
#pragma unroll
        for (int mt = 0; mt < 2; mt++)
#pragma unroll
            for (int nt = 0; nt < 2; nt++)
#pragma unroll
                for (int ci = 0; ci < 4; ci++) {
                    int m = m0 + mt * 16 + g + ((ci >> 1) * 8);
                    int tl = n0 + nt * 8 + tq * 2 + (ci & 1);
                    float y = fmaxf(acc[mt][nt][ci], 0.f);
                    __nv_bfloat16 h = __float2bfloat16(y);
                    __nv_bfloat16 l = __float2bfloat16(y - __bfloat162float(h));
                    stg[tl * 136 + m] = __bfloat16_as_ushort(h);
                    stg[4352 + tl * 136 + m] = __bfloat16_as_ushort(l);
                }
        __syncthreads();

        const int tcb = tbase + c * CHUNK;
#pragma unroll
        for (int i = 0; i < 4; i++) {
            int idx = i * 256 + tid;   // 1024 uint4
            int pl = idx >> 9, rem = idx & 511;
            int r = rem >> 4, sg = rem & 15;
            uint4 v = *(const uint4*)(stg + pl * 4352 + r * 136 + sg * 8);
            *(uint4*)(actout + ((size_t)(n * 2 + pl) * T_LEN + tcb + r) * CH + sg * 8) = v;
        }
        __syncthreads();   // stage reads done before cp.async reuses the buffer

        if (c + 2 < NCHUNK) {
            load_x(c + 2);
            CP_WAIT1();
        } else if (c + 1 < NCHUNK) {
            CP_WAIT0();
        }
        __syncthreads();
    }
}

// ---------------- classifier: 128 -> 256, + bias, no relu ----------------
// smem (u32): [0,17408) WC [pl][128][68]; [17408, 26112) X [buf2][pl2][32][68]
__global__ void __launch_bounds__(256, 1) cls_mma(
    const unsigned short* __restrict__ actin,
    const uint32_t* __restrict__ wc,
    const float* __restrict__ bias,
    float* __restrict__ out) {
    extern __shared__ uint32_t sm[];
    const uint32_t sb = smem_u32(sm);
    const int tid = threadIdx.x;
    const int lane = tid & 31, wid = tid >> 5;
    const int g = lane >> 2, tq = lane & 3;
    const int n = blockIdx.y;
    const int tbase = blockIdx.x * SPAN;
    const int mz = blockIdx.z * 128;
    const int m0 = (wid & 3) * 32;
    const int n0 = (wid >> 2) * 16;

    // WC -> smem (both planes for this m-tile)
#pragma unroll
    for (int i = 0; i < 16; i++) {
        int idx = i * 256 + tid;
        int row = idx >> 4, seg = idx & 15;   // row = pl*128 + m
        const uint32_t* src = wc + ((size_t)(row >> 7) * 256 + mz + (row & 127)) * 64 + seg * 4;
        cpa16(sb + (row * 68 + seg * 4) * 4, src, 16);
    }
    CP_COMMIT();

    auto load_x = [&](int c) {
        int buf = c & 1;
        int tcb = tbase + c * CHUNK;
#pragma unroll
        for (int i = 0; i < 4; i++) {
            int idx = i * 256 + tid;   // 1024 segs
            int pl = idx >> 9, rem = idx & 511;
            int r = rem >> 4, seg = rem & 15;
            const unsigned short* src =
                actin + ((size_t)(n * 2 + pl) * T_LEN + tcb + r) * CH + seg * 8;
            cpa16(sb + (17408 + buf * 4352 + pl * 2176 + r * 68 + seg * 4) * 4, src, 16);
        }
        CP_COMMIT();
    };
    load_x(0);
    load_x(1);
    CP_WAIT1();
    __syncthreads();

#pragma unroll 1
    for (int c = 0; c < NCHUNK; c++) {
        const int buf = c & 1;
        const uint32_t* X = sm + 17408 + buf * 4352;

        float acc[2][2][4];
#pragma unroll
        for (int mt = 0; mt < 2; mt++)
#pragma unroll
            for (int nt = 0; nt < 2; nt++)
#pragma unroll
                for (int j = 0; j < 4; j++) acc[mt][nt][j] = 0.f;

#pragma unroll
        for (int pass = 0; pass < 3; pass++) {
            const int wp = (pass == 2) ? 1 : 0;
            const int xp = (pass == 1) ? 1 : 0;
            const uint32_t* Wt = sm + wp * 8704;
            const uint32_t* Xt = X + xp * 2176;
#pragma unroll
            for (int ks = 0; ks < 8; ks++) {
                uint32_t a[2][4], b0[2], b1[2];
#pragma unroll
                for (int mt = 0; mt < 2; mt++) {
                    a[mt][0] = Wt[(m0 + mt * 16 + g) * 68 + ks * 8 + tq];
                    a[mt][1] = Wt[(m0 + mt * 16 + g + 8) * 68 + ks * 8 + tq];
                    a[mt][2] = Wt[(m0 + mt * 16 + g) * 68 + ks * 8 + 4 + tq];
                    a[mt][3] = Wt[(m0 + mt * 16 + g + 8) * 68 + ks * 8 + 4 + tq];
                }
#pragma unroll
                for (int nt = 0; nt < 2; nt++) {
                    const uint32_t* xr = Xt + (n0 + nt * 8 + g) * 68;
                    b0[nt] = xr[ks * 8 + tq];
                    b1[nt] = xr[ks * 8 + 4 + tq];
                }
#pragma unroll
                for (int mt = 0; mt < 2; mt++)
#pragma unroll
                    for (int nt = 0; nt < 2; nt++)
                        mma16816(acc[mt][nt], a[mt], b0[nt], b1[nt]);
            }
        }

        __syncthreads();
        // epilogue: + bias, transpose through smem [m][34 f32], coalesced out
        float* stg = (float*)(sm + 17408 + buf * 4352);
#pragma unroll
        for (int mt = 0; mt < 2; mt++)
#pragma unroll
            for (int nt = 0; nt < 2; nt++)
#pragma unroll
                for (int ci = 0; ci < 4; ci++) {
                    int m = m0 + mt * 16 + g + ((ci >> 1) * 8);
                    int tl = n0 + nt * 8 + tq * 2 + (ci & 1);
                    stg[m * 34 + tl] = acc[mt][nt][ci] + __ldg(bias + mz + m);
                }
        __syncthreads();

        const int tcb = tbase + c * CHUNK;
#pragma unroll
        for (int i = 0; i < 8; i++) {
            int idx = i * 256 + tid;   // 2048 float2
            int row = idx >> 4, sg = idx & 15;
            float2 v = *(const float2*)(stg + row * 34 + sg * 2);
            *(float2*)(out + ((size_t)n * NCLS + mz + row) * T_LEN + tcb + sg * 2) = v;
        }
        __syncthreads();

        if (c + 2 < NCHUNK) {
            load_x(c + 2);
            CP_WAIT1();
        } else if (c + 1 < NCHUNK) {
            CP_WAIT0();
        }
        __syncthreads();
    }
}

// ---------------- launch ----------------
extern "C" void kernel_launch(void* const* d_in, const int* in_sizes, int n_in,
                              void* d_out, int out_size) {
    (void)in_sizes; (void)n_in; (void)out_size;
    const float* seq     = (const float*)d_in[0];
    const float* w_first = (const float*)d_in[1];
    const float* w_rest  = (const float*)d_in[2];
    const float* w_cls   = (const float*)d_in[3];
    const float* b_cls   = (const float*)d_in[4];
    float* out = (float*)d_out;

    unsigned short *a0, *a1;
    uint32_t *whi, *wlo, *wc;
    cudaGetSymbolAddress((void**)&a0, g_act0);
    cudaGetSymbolAddress((void**)&a1, g_act1);
    cudaGetSymbolAddress((void**)&whi, g_whi);
    cudaGetSymbolAddress((void**)&wlo, g_wlo);
    cudaGetSymbolAddress((void**)&wc, g_wc);

    const int smem_layer = 34816 * 4;  // 139264 B
    const int smem_cls   = 26112 * 4;  // 104448 B
    cudaFuncSetAttribute(layer_mma, cudaFuncAttributeMaxDynamicSharedMemorySize, smem_layer);
    cudaFuncSetAttribute(cls_mma, cudaFuncAttributeMaxDynamicSharedMemorySize, smem_cls);

    prep_kernel<<<(27 * 2 * 128 * 64 + 255) / 256, 256>>>(w_rest, w_cls, whi, wlo, wc);
    layer0_kernel<<<dim3(T_LEN / 128, NB), 256>>>(seq, w_first, a0);

    for (int i = 1; i < 28; i++) {
        int l = i % 14;
        int d = 1 << (l % 10);
        const unsigned short* src = (i & 1) ? a0 : a1;
        unsigned short* dst       = (i & 1) ? a1 : a0;
        layer_mma<<<dim3(NXCTA, NB), 256, smem_layer>>>(
            src, dst, whi + (size_t)(i - 1) * 2 * 128 * 64,
            wlo + (size_t)(i - 1) * 2 * 128 * 64, d);
    }

    cls_mma<<<dim3(NXCTA, NB, 2), 256, smem_cls>>>(a1, wc, b_cls, out);
}

// round 5
// speedup vs baseline: 1.7836x; 1.0163x over previous
#include <cuda_runtime.h>
#include <cuda_bf16.h>
#include <cstdint>

#define T_LEN 64000
#define NB 4
#define CH 128
#define NCLS 256
#define CHUNK 32
#define NCHUNK 8
#define SPAN (CHUNK * NCHUNK)      // 256 t per CTA
#define NXCTA (T_LEN / SPAN)       // 250

// ---------------- static device buffers ----------------
__device__ unsigned short g_act0[(size_t)NB * 2 * T_LEN * CH];
__device__ unsigned short g_act1[(size_t)NB * 2 * T_LEN * CH];
__device__ uint32_t g_whi[27 * 2 * 128 * 64];
__device__ uint32_t g_wlo[27 * 2 * 128 * 64];
__device__ uint32_t g_wc[2 * 256 * 64];

// ---------------- helpers ----------------
__device__ __forceinline__ uint32_t smem_u32(const void* p) {
    uint32_t a;
    asm("{ .reg .u64 t; cvta.to.shared.u64 t, %1; cvt.u32.u64 %0, t; }" : "=r"(a) : "l"(p));
    return a;
}
__device__ __forceinline__ void cpa16(uint32_t dst, const void* src, int sz) {
    asm volatile("cp.async.cg.shared.global [%0], [%1], 16, %2;"
                 :: "r"(dst), "l"(src), "r"(sz) : "memory");
}
#define CP_COMMIT() asm volatile("cp.async.commit_group;" ::: "memory")
#define CP_WAIT1()  asm volatile("cp.async.wait_group 1;" ::: "memory")
#define CP_WAIT0()  asm volatile("cp.async.wait_group 0;" ::: "memory")

__device__ __forceinline__ void mma16816(float c[4], const uint32_t a[4],
                                         uint32_t b0, uint32_t b1) {
    asm volatile(
        "mma.sync.aligned.m16n8k16.row.col.f32.bf16.bf16.f32 "
        "{%0,%1,%2,%3}, {%4,%5,%6,%7}, {%8,%9}, {%0,%1,%2,%3};"
        : "+f"(c[0]), "+f"(c[1]), "+f"(c[2]), "+f"(c[3])
        : "r"(a[0]), "r"(a[1]), "r"(a[2]), "r"(a[3]), "r"(b0), "r"(b1));
}

// ---------------- prep: split + pack weights ----------------
__device__ __forceinline__ uint32_t pack_split(float w0, float w1, int plane) {
    __nv_bfloat16 h0 = __float2bfloat16(w0), h1 = __float2bfloat16(w1);
    if (plane == 0)
        return (uint32_t)__bfloat16_as_ushort(h0) |
               ((uint32_t)__bfloat16_as_ushort(h1) << 16);
    __nv_bfloat16 l0 = __float2bfloat16(w0 - __bfloat162float(h0));
    __nv_bfloat16 l1 = __float2bfloat16(w1 - __bfloat162float(h1));
    return (uint32_t)__bfloat16_as_ushort(l0) |
           ((uint32_t)__bfloat16_as_ushort(l1) << 16);
}

__global__ void prep_kernel(const float* __restrict__ wrest,
                            const float* __restrict__ wcls,
                            uint32_t* __restrict__ whi,
                            uint32_t* __restrict__ wlo,
                            uint32_t* __restrict__ wc) {
    int idx = blockIdx.x * blockDim.x + threadIdx.x;
    if (idx < 27 * 2 * 128 * 64) {
        int kp = idx & 63;
        int m = (idx >> 6) & 127;
        int tap = (idx >> 13) & 1;
        int L = idx >> 14;
        float w0 = wrest[((L * 128 + m) * 128 + kp * 2) * 2 + tap];
        float w1 = wrest[((L * 128 + m) * 128 + kp * 2 + 1) * 2 + tap];
        whi[idx] = pack_split(w0, w1, 0);
        wlo[idx] = pack_split(w0, w1, 1);
    }
    if (idx < 2 * 256 * 64) {
        int kp = idx & 63;
        int m = (idx >> 6) & 255;
        int pl = idx >> 14;
        float w0 = wcls[m * 128 + kp * 2];
        float w1 = wcls[m * 128 + kp * 2 + 1];
        wc[idx] = pack_split(w0, w1, pl);
    }
}

// ---------------- layer 0 ----------------
__global__ void layer0_kernel(const float* __restrict__ seq,
                              const float* __restrict__ wf,
                              unsigned short* __restrict__ actout) {
    int oc = threadIdx.x & 127;
    int half = threadIdx.x >> 7;
    int n = blockIdx.y;
    int t0 = blockIdx.x * 128 + half * 64;
    float w0 = wf[oc * 2], w1 = wf[oc * 2 + 1];
    const float* xs = seq + (size_t)n * T_LEN;
    unsigned short* ohi = actout + (size_t)(n * 2 + 0) * T_LEN * CH;
    unsigned short* olo = actout + (size_t)(n * 2 + 1) * T_LEN * CH;
    for (int j = 0; j < 64; j++) {
        int t = t0 + j;
        float x1 = xs[t];
        float x0 = (t >= 1) ? xs[t - 1] : 0.f;
        float y = fmaxf(w0 * x0 + w1 * x1, 0.f);
        __nv_bfloat16 h = __float2bfloat16(y);
        __nv_bfloat16 l = __float2bfloat16(y - __bfloat162float(h));
        ohi[(size_t)t * CH + oc] = __bfloat16_as_ushort(h);
        olo[(size_t)t * CH + oc] = __bfloat16_as_ushort(l);
    }
}

// ---------------- dilated-conv layer via mma.sync bf16 ----------------
// smem (u32 units):
//   [0, 17408)        Wl: [tap][m 128][68]
//   [17408, 34816)    X : [buf 2][tile 4 = tap*2+plane][r 32][68]
//   [34816, 39168)    stage: u16[2 pl][32 t][136 m]
__global__ void __launch_bounds__(256, 1) layer_mma(
    const unsigned short* __restrict__ actin,
    unsigned short* __restrict__ actout,
    const uint32_t* __restrict__ whi,
    const uint32_t* __restrict__ wlo, int d) {
    extern __shared__ uint32_t sm[];
    const uint32_t sb = smem_u32(sm);
    const int tid = threadIdx.x;
    const int lane = tid & 31, wid = tid >> 5;
    const int g = lane >> 2, tq = lane & 3;
    const int n = blockIdx.y;
    const int tbase = blockIdx.x * SPAN;
    const int m0 = (wid & 3) * 32;
    const int n0 = (wid >> 2) * 16;

    // ---- group 0: Wl -> smem
#pragma unroll
    for (int i = 0; i < 16; i++) {
        int idx = i * 256 + tid;
        int row = idx >> 4, seg = idx & 15;
        cpa16(sb + (row * 68 + seg * 4) * 4, wlo + row * 64 + seg * 4, 16);
    }
    CP_COMMIT();

    auto load_x = [&](int c) {
        int buf = c & 1;
        int tcb = tbase + c * CHUNK;
#pragma unroll
        for (int i = 0; i < 8; i++) {
            int idx = i * 256 + tid;
            int tile = idx >> 9, rem = idx & 511;
            int r = rem >> 4, seg = rem & 15;
            int tap = tile >> 1, pl = tile & 1;
            int t = tcb + r - (tap == 0 ? d : 0);
            const unsigned short* src =
                actin + ((size_t)(n * 2 + pl) * T_LEN + (t < 0 ? 0 : t)) * CH + seg * 8;
            cpa16(sb + (17408 + buf * 8704 + tile * 2176 + r * 68 + seg * 4) * 4,
                  src, t >= 0 ? 16 : 0);
        }
        CP_COMMIT();
    };
    load_x(0);
    load_x(1);

    // ---- preload Wh fragments into registers (chunk-invariant)
    uint32_t wh[2][8][2][4];
#pragma unroll
    for (int tap = 0; tap < 2; tap++)
#pragma unroll
        for (int ks = 0; ks < 8; ks++)
#pragma unroll
            for (int mt = 0; mt < 2; mt++) {
                const uint32_t* wp = whi + (tap * 128 + m0 + mt * 16) * 64;
                wh[tap][ks][mt][0] = wp[(g)*64 + ks * 8 + tq];
                wh[tap][ks][mt][1] = wp[(g + 8) * 64 + ks * 8 + tq];
                wh[tap][ks][mt][2] = wp[(g)*64 + ks * 8 + 4 + tq];
                wh[tap][ks][mt][3] = wp[(g + 8) * 64 + ks * 8 + 4 + tq];
            }

    CP_WAIT1();          // Wl + chunk0 complete (chunk1 in flight)
    __syncthreads();

    unsigned short* stg = (unsigned short*)(sm + 34816);

#pragma unroll 1
    for (int c = 0; c < NCHUNK; c++) {
        const int buf = c & 1;
        const uint32_t* X = sm + 17408 + buf * 8704;

        float acc[2][2][4];
#pragma unroll
        for (int mt = 0; mt < 2; mt++)
#pragma unroll
            for (int nt = 0; nt < 2; nt++)
#pragma unroll
                for (int j = 0; j < 4; j++) acc[mt][nt][j] = 0.f;

        // -- passes 1,2: Wh (regs) x {Xh, Xl}
#pragma unroll
        for (int xpl = 0; xpl < 2; xpl++)
#pragma unroll
            for (int tap = 0; tap < 2; tap++) {
                const uint32_t* Xt = X + (tap * 2 + xpl) * 2176;
#pragma unroll
                for (int ks = 0; ks < 8; ks++) {
                    uint32_t b0[2], b1[2];
#pragma unroll
                    for (int nt = 0; nt < 2; nt++) {
                        const uint32_t* xr = Xt + (n0 + nt * 8 + g) * 68;
                        b0[nt] = xr[ks * 8 + tq];
                        b1[nt] = xr[ks * 8 + 4 + tq];
                    }
#pragma unroll
                    for (int mt = 0; mt < 2; mt++)
#pragma unroll
                        for (int nt = 0; nt < 2; nt++)
                            mma16816(acc[mt][nt], wh[tap][ks][mt], b0[nt], b1[nt]);
                }
            }

        // -- pass 3: Wl (smem) x Xh
#pragma unroll
        for (int tap = 0; tap < 2; tap++) {
            const uint32_t* Xt = X + (tap * 2 + 0) * 2176;
            const uint32_t* Wt = sm + tap * 8704;
#pragma unroll
            for (int ks = 0; ks < 8; ks++) {
                uint32_t a[2][4], b0[2], b1[2];
#pragma unroll
                for (int mt = 0; mt < 2; mt++) {
                    a[mt][0] = Wt[(m0 + mt * 16 + g) * 68 + ks * 8 + tq];
                    a[mt][1] = Wt[(m0 + mt * 16 + g + 8) * 68 + ks * 8 + tq];
                    a[mt][2] = Wt[(m0 + mt * 16 + g) * 68 + ks * 8 + 4 + tq];
                    a[mt][3] = Wt[(m0 + mt * 16 + g + 8) * 68 + ks * 8 + 4 + tq];
                }
#pragma unroll
                for (int nt = 0; nt < 2; nt++) {
                    const uint32_t* xr = Xt + (n0 + nt * 8 + g) * 68;
                    b0[nt] = xr[ks * 8 + tq];
                    b1[nt] = xr[ks * 8 + 4 + tq];
                }
#pragma unroll
                for (int mt = 0; mt < 2; mt++)
#pragma unroll
                    for (int nt = 0; nt < 2; nt++)
                        mma16816(acc[mt][nt], a[mt], b0[nt], b1[nt]);
            }
        }

        __syncthreads();  // X[buf] reads done by all warps; stage(prev) reads done

        // prefetch chunk c+2 into buf — overlaps epilogue AND next chunk MMA
        if (c + 2 < NCHUNK) load_x(c + 2);

        // -- epilogue: relu + split into dedicated stage
#pragma unroll
        for (int mt = 0; mt < 2; mt++)
#pragma unroll
            for (int nt = 0; nt < 2; nt++)
#pragma unroll
                for (int ci = 0; ci < 4; ci++) {
                    int m = m0 + mt * 16 + g + ((ci >> 1) * 8);
                    int tl = n0 + nt * 8 + tq * 2 + (ci & 1);
                    float y = fmaxf(acc[mt][nt][ci], 0.f);
                    __nv_bfloat16 h = __float2bfloat16(y);
                    __nv_bfloat16 l = __float2bfloat16(y - __bfloat162float(h));
                    stg[tl * 136 + m] = __bfloat16_as_ushort(h);
                    stg[4352 + tl * 136 + m] = __bfloat16_as_ushort(l);
                }

        if (c + 1 < NCHUNK) {
            if (c + 2 < NCHUNK) CP_WAIT1();
            else CP_WAIT0();
        }
        __syncthreads();  // stage visible + chunk c+1 cp data visible

        // coalesced stores; overlap with next chunk's MMA (no trailing barrier)
        const int tcb = tbase + c * CHUNK;
#pragma unroll
        for (int i = 0; i < 4; i++) {
            int idx = i * 256 + tid;
            int pl = idx >> 9, rem = idx & 511;
            int r = rem >> 4, sg = rem & 15;
            uint4 v = *(const uint4*)(stg + pl * 4352 + r * 136 + sg * 8);
            *(uint4*)(actout + ((size_t)(n * 2 + pl) * T_LEN + tcb + r) * CH + sg * 8) = v;
        }
    }
}

// ---------------- classifier: 128 -> 256, + bias, no relu ----------------
// smem (u32): [0,17408) WC [pl][128][68]; [17408,26112) X [buf2][pl2][32][68];
//             [26112,30464) stage f32 [128][34]
__global__ void __launch_bounds__(256, 1) cls_mma(
    const unsigned short* __restrict__ actin,
    const uint32_t* __restrict__ wc,
    const float* __restrict__ bias,
    float* __restrict__ out) {
    extern __shared__ uint32_t sm[];
    const uint32_t sb = smem_u32(sm);
    const int tid = threadIdx.x;
    const int lane = tid & 31, wid = tid >> 5;
    const int g = lane >> 2, tq = lane & 3;
    const int n = blockIdx.y;
    const int tbase = blockIdx.x * SPAN;
    const int mz = blockIdx.z * 128;
    const int m0 = (wid & 3) * 32;
    const int n0 = (wid >> 2) * 16;

#pragma unroll
    for (int i = 0; i < 16; i++) {
        int idx = i * 256 + tid;
        int row = idx >> 4, seg = idx & 15;
        const uint32_t* src = wc + ((size_t)(row >> 7) * 256 + mz + (row & 127)) * 64 + seg * 4;
        cpa16(sb + (row * 68 + seg * 4) * 4, src, 16);
    }
    CP_COMMIT();

    auto load_x = [&](int c) {
        int buf = c & 1;
        int tcb = tbase + c * CHUNK;
#pragma unroll
        for (int i = 0; i < 4; i++) {
            int idx = i * 256 + tid;
            int pl = idx >> 9, rem = idx & 511;
            int r = rem >> 4, seg = rem & 15;
            const unsigned short* src =
                actin + ((size_t)(n * 2 + pl) * T_LEN + tcb + r) * CH + seg * 8;
            cpa16(sb + (17408 + buf * 4352 + pl * 2176 + r * 68 + seg * 4) * 4, src, 16);
        }
        CP_COMMIT();
    };
    load_x(0);
    load_x(1);
    CP_WAIT1();
    __syncthreads();

    float* stg = (float*)(sm + 26112);

#pragma unroll 1
    for (int c = 0; c < NCHUNK; c++) {
        const int buf = c & 1;
        const uint32_t* X = sm + 17408 + buf * 4352;

        float acc[2][2][4];
#pragma unroll
        for (int mt = 0; mt < 2; mt++)
#pragma unroll
            for (int nt = 0; nt < 2; nt++)
#pragma unroll
                for (int j = 0; j < 4; j++) acc[mt][nt][j] = 0.f;

#pragma unroll
        for (int pass = 0; pass < 3; pass++) {
            const int wp = (pass == 2) ? 1 : 0;
            const int xp = (pass == 1) ? 1 : 0;
            const uint32_t* Wt = sm + wp * 8704;
            const uint32_t* Xt = X + xp * 2176;
#pragma unroll
            for (int ks = 0; ks < 8; ks++) {
                uint32_t a[2][4], b0[2], b1[2];
#pragma unroll
                for (int mt = 0; mt < 2; mt++) {
                    a[mt][0] = Wt[(m0 + mt * 16 + g) * 68 + ks * 8 + tq];
                    a[mt][1] = Wt[(m0 + mt * 16 + g + 8) * 68 + ks * 8 + tq];
                    a[mt][2] = Wt[(m0 + mt * 16 + g) * 68 + ks * 8 + 4 + tq];
                    a[mt][3] = Wt[(m0 + mt * 16 + g + 8) * 68 + ks * 8 + 4 + tq];
                }
#pragma unroll
                for (int nt = 0; nt < 2; nt++) {
                    const uint32_t* xr = Xt + (n0 + nt * 8 + g) * 68;
                    b0[nt] = xr[ks * 8 + tq];
                    b1[nt] = xr[ks * 8 + 4 + tq];
                }
#pragma unroll
                for (int mt = 0; mt < 2; mt++)
#pragma unroll
                    for (int nt = 0; nt < 2; nt++)
                        mma16816(acc[mt][nt], a[mt], b0[nt], b1[nt]);
            }
        }

        __syncthreads();
        if (c + 2 < NCHUNK) load_x(c + 2);

#pragma unroll
        for (int mt = 0; mt < 2; mt++)
#pragma unroll
            for (int nt = 0; nt < 2; nt++)
#pragma unroll
                for (int ci = 0; ci < 4; ci++) {
                    int m = m0 + mt * 16 + g + ((ci >> 1) * 8);
                    int tl = n0 + nt * 8 + tq * 2 + (ci & 1);
                    stg[m * 34 + tl] = acc[mt][nt][ci] + __ldg(bias + mz + m);
                }

        if (c + 1 < NCHUNK) {
            if (c + 2 < NCHUNK) CP_WAIT1();
            else CP_WAIT0();
        }
        __syncthreads();

        const int tcb = tbase + c * CHUNK;
#pragma unroll
        for (int i = 0; i < 8; i++) {
            int idx = i * 256 + tid;
            int row = idx >> 4, sg = idx & 15;
            float2 v = *(const float2*)(stg + row * 34 + sg * 2);
            *(float2*)(out + ((size_t)n * NCLS + mz + row) * T_LEN + tcb + sg * 2) = v;
        }
    }
}

// ---------------- launch ----------------
extern "C" void kernel_launch(void* const* d_in, const int* in_sizes, int n_in,
                              void* d_out, int out_size) {
    (void)in_sizes; (void)n_in; (void)out_size;
    const float* seq     = (const float*)d_in[0];
    const float* w_first = (const float*)d_in[1];
    const float* w_rest  = (const float*)d_in[2];
    const float* w_cls   = (const float*)d_in[3];
    const float* b_cls   = (const float*)d_in[4];
    float* out = (float*)d_out;

    unsigned short *a0, *a1;
    uint32_t *whi, *wlo, *wc;
    cudaGetSymbolAddress((void**)&a0, g_act0);
    cudaGetSymbolAddress((void**)&a1, g_act1);
    cudaGetSymbolAddress((void**)&whi, g_whi);
    cudaGetSymbolAddress((void**)&wlo, g_wlo);
    cudaGetSymbolAddress((void**)&wc, g_wc);

    const int smem_layer = 39168 * 4;  // 156672 B
    const int smem_cls   = 30464 * 4;  // 121856 B
    cudaFuncSetAttribute(layer_mma, cudaFuncAttributeMaxDynamicSharedMemorySize, smem_layer);
    cudaFuncSetAttribute(cls_mma, cudaFuncAttributeMaxDynamicSharedMemorySize, smem_cls);

    prep_kernel<<<(27 * 2 * 128 * 64 + 255) / 256, 256>>>(w_rest, w_cls, whi, wlo, wc);
    layer0_kernel<<<dim3(T_LEN / 128, NB), 256>>>(seq, w_first, a0);

    for (int i = 1; i < 28; i++) {
        int l = i % 14;
        int d = 1 << (l % 10);
        const unsigned short* src = (i & 1) ? a0 : a1;
        unsigned short* dst       = (i & 1) ? a1 : a0;
        layer_mma<<<dim3(NXCTA, NB), 256, smem_layer>>>(
            src, dst, whi + (size_t)(i - 1) * 2 * 128 * 64,
            wlo + (size_t)(i - 1) * 2 * 128 * 64, d);
    }

    cls_mma<<<dim3(NXCTA, NB, 2), 256, smem_cls>>>(a1, wc, b_cls, out);
}